// round 1
// baseline (speedup 1.0000x reference)
#include <cuda_runtime.h>
#include <cstdint>
#include <cstddef>

// ---------------------------------------------------------------------------
// Problem dims (fixed by reference)
// ---------------------------------------------------------------------------
#define BB    8
#define TT    1024
#define CC    512
#define LL    12
#define VV    8000
#define RR    64
#define ARR   32
#define FFNN  2048
#define MM    (BB * TT)          // 8192 rows
#define LOGITS_ELEMS ((size_t)MM * VV)   // 65,536,000

// ---------------------------------------------------------------------------
// Scratch (static device memory; no allocations allowed)
// ---------------------------------------------------------------------------
__device__ float g_x  [MM * CC];
__device__ float g_xm [MM * CC];
__device__ float g_mix[MM * CC];
__device__ float g_q  [MM * CC];
__device__ float g_k  [MM * CC];
__device__ float g_v  [MM * CC];
__device__ float g_y  [MM * CC];
__device__ float g_x2 [MM * CC];
__device__ float g_ffn[MM * FFNN];
__device__ float g_tq [MM * RR];
__device__ float g_tk [MM * RR];
__device__ float g_tv [MM * RR];
__device__ float g_ad [MM * ARR];

// ---------------------------------------------------------------------------
// Helpers
// ---------------------------------------------------------------------------
__device__ __forceinline__ float gelu_tanh(float x) {
    // JAX default gelu (approximate=True)
    float x3 = x * x * x;
    return 0.5f * x * (1.0f + tanhf(0.7978845608028654f * (x + 0.044715f * x3)));
}

__device__ __forceinline__ float blockReduceSum(float v) {
    static __shared__ float sb[8];
    int tid = threadIdx.x;
#pragma unroll
    for (int o = 16; o > 0; o >>= 1) v += __shfl_down_sync(0xffffffffu, v, o);
    __syncthreads();                      // protect sb across back-to-back calls
    if ((tid & 31) == 0) sb[tid >> 5] = v;
    __syncthreads();
    if (tid < 32) {
        v = (tid < 8) ? sb[tid] : 0.0f;
#pragma unroll
        for (int o = 4; o > 0; o >>= 1) v += __shfl_down_sync(0xffffffffu, v, o);
        if (tid == 0) sb[0] = v;
    }
    __syncthreads();
    return sb[0];
}

// ---------------------------------------------------------------------------
// Embedding gather: x[r,:] = embed[ids[r],:]
// grid = MM, block = 128 (float4 per thread => 512 floats)
// ---------------------------------------------------------------------------
__global__ void gather_kernel(const int* __restrict__ ids,
                              const float* __restrict__ embed,
                              float* __restrict__ x) {
    int r = blockIdx.x;
    int id = ids[r];
    const float4* er = (const float4*)(embed + (size_t)id * CC);
    float4* xr = (float4*)(x + (size_t)r * CC);
    xr[threadIdx.x] = er[threadIdx.x];
}

// ---------------------------------------------------------------------------
// Fused double layernorm: xm = LN2(LN1(x))
// grid = MM rows, block = 256 (2 elems / thread)
// ---------------------------------------------------------------------------
__global__ void ln12_kernel(const float* __restrict__ x,
                            const float* __restrict__ g1, const float* __restrict__ b1,
                            const float* __restrict__ g2, const float* __restrict__ b2,
                            float* __restrict__ out) {
    int r = blockIdx.x, tid = threadIdx.x;
    const float* xr = x + (size_t)r * CC;
    float a0 = xr[tid], a1 = xr[tid + 256];

    float m = blockReduceSum(a0 + a1) * (1.0f / CC);
    float d0 = a0 - m, d1 = a1 - m;
    float var = blockReduceSum(d0 * d0 + d1 * d1) * (1.0f / CC);
    float inv = rsqrtf(var + 1e-5f);
    float xi0 = d0 * inv * g1[tid]       + b1[tid];
    float xi1 = d1 * inv * g1[tid + 256] + b1[tid + 256];

    float m2 = blockReduceSum(xi0 + xi1) * (1.0f / CC);
    float e0 = xi0 - m2, e1 = xi1 - m2;
    float var2 = blockReduceSum(e0 * e0 + e1 * e1) * (1.0f / CC);
    float inv2 = rsqrtf(var2 + 1e-5f);
    out[(size_t)r * CC + tid]       = e0 * inv2 * g2[tid]       + b2[tid];
    out[(size_t)r * CC + tid + 256] = e1 * inv2 * g2[tid + 256] + b2[tid + 256];
}

// Single layernorm
__global__ void ln_kernel(const float* __restrict__ x,
                          const float* __restrict__ g, const float* __restrict__ b,
                          float* __restrict__ out) {
    int r = blockIdx.x, tid = threadIdx.x;
    const float* xr = x + (size_t)r * CC;
    float a0 = xr[tid], a1 = xr[tid + 256];
    float m = blockReduceSum(a0 + a1) * (1.0f / CC);
    float d0 = a0 - m, d1 = a1 - m;
    float var = blockReduceSum(d0 * d0 + d1 * d1) * (1.0f / CC);
    float inv = rsqrtf(var + 1e-5f);
    out[(size_t)r * CC + tid]       = d0 * inv * g[tid]       + b[tid];
    out[(size_t)r * CC + tid + 256] = d1 * inv * g[tid + 256] + b[tid + 256];
}

// ---------------------------------------------------------------------------
// mix = 0.5*xm[t] + 0.5*xm[t-1]  (zero at t==0 per batch)
// ---------------------------------------------------------------------------
__global__ void mix_kernel(const float* __restrict__ xm, float* __restrict__ mix) {
    size_t idx = (size_t)blockIdx.x * blockDim.x + threadIdx.x;
    int m = (int)(idx >> 9);            // /CC
    float v = 0.5f * xm[idx];
    if (m & (TT - 1)) v += 0.5f * xm[idx - CC];
    mix[idx] = v;
}

// ---------------------------------------------------------------------------
// WKV scan: one thread per (b, c) lane; serial over T.
// h_t = d*h + k*v ; y_t = sigmoid(q)*h.  Writes final h into d_out slice.
// grid = 16, block = 256 (4096 lanes)
// ---------------------------------------------------------------------------
__global__ void wkv_kernel(const float* __restrict__ q,
                           const float* __restrict__ k,
                           const float* __restrict__ v,
                           const float* __restrict__ time_decay,  // [CC] (layer row)
                           float* __restrict__ y,
                           float* __restrict__ hout) {            // [BB*CC]
    int idx = blockIdx.x * blockDim.x + threadIdx.x;  // 0..4095
    int b = idx >> 9;
    int c = idx & (CC - 1);
    float d = expf(-expf(time_decay[c]));
    size_t base = (size_t)b * TT * CC + c;
    const float* qp = q + base;
    const float* kp = k + base;
    const float* vp = v + base;
    float* yp = y + base;
    float h = 0.0f;
#pragma unroll 4
    for (int t = 0; t < TT; t++) {
        size_t off = (size_t)t * CC;
        float qt = qp[off], kt = kp[off], vt = vp[off];
        h = d * h + kt * vt;
        yp[off] = h / (1.0f + expf(-qt));
    }
    hout[idx] = h;
}

// ---------------------------------------------------------------------------
// Generic tiled SGEMM with fused epilogues.
//  C[M,N] (+)= A[M,K] * B[K,N]   (BT=true: B stored [N,K], i.e. C = A * B^T)
//  EPI: 0 store | 1 gelu(acc+bias) | 2 relu(acc) | 3 C += acc + bias | 4 C += acc
// grid = (N/BN, M/BM), block = (BM/TM)*(BN/TN) = 256. All dims divide exactly.
// ---------------------------------------------------------------------------
template<int BM, int BN, int BK, int TM, int TN, int EPI, bool BT>
__global__ __launch_bounds__(256) void sgemm_kernel(
        const float* __restrict__ A, const float* __restrict__ B,
        const float* __restrict__ bias, float* __restrict__ C,
        int M, int N, int K) {
    constexpr int THREADS = (BM / TM) * (BN / TN);
    static_assert(THREADS == 256, "block must be 256 threads");
    __shared__ float As[BK][BM + 4];
    __shared__ float Bs[BK][BN];

    const int tid = threadIdx.x;
    const int tx = tid % (BN / TN);
    const int ty = tid / (BN / TN);
    const int m0 = blockIdx.y * BM;
    const int n0 = blockIdx.x * BN;

    float acc[TM][TN];
#pragma unroll
    for (int i = 0; i < TM; i++)
#pragma unroll
        for (int j = 0; j < TN; j++) acc[i][j] = 0.0f;

    for (int k0 = 0; k0 < K; k0 += BK) {
#pragma unroll
        for (int i = tid; i < BM * BK; i += THREADS) {
            int m = i / BK, k = i % BK;
            As[k][m] = A[(size_t)(m0 + m) * K + k0 + k];
        }
        if (!BT) {
#pragma unroll
            for (int i = tid; i < BK * BN; i += THREADS) {
                int k = i / BN, n = i % BN;
                Bs[k][n] = B[(size_t)(k0 + k) * N + n0 + n];
            }
        } else {
#pragma unroll
            for (int i = tid; i < BK * BN; i += THREADS) {
                int n = i / BK, k = i % BK;
                Bs[k][n] = B[(size_t)(n0 + n) * K + k0 + k];
            }
        }
        __syncthreads();
#pragma unroll
        for (int k = 0; k < BK; k++) {
            float ra[TM], rb[TN];
#pragma unroll
            for (int i = 0; i < TM; i++) ra[i] = As[k][ty * TM + i];
#pragma unroll
            for (int j = 0; j < TN; j++) rb[j] = Bs[k][tx * TN + j];
#pragma unroll
            for (int i = 0; i < TM; i++)
#pragma unroll
                for (int j = 0; j < TN; j++) acc[i][j] = fmaf(ra[i], rb[j], acc[i][j]);
        }
        __syncthreads();
    }

    const int mbase = m0 + ty * TM;
    const int nbase = n0 + tx * TN;
#pragma unroll
    for (int i = 0; i < TM; i++) {
#pragma unroll
        for (int j = 0; j < TN; j++) {
            size_t off = (size_t)(mbase + i) * N + nbase + j;
            float val = acc[i][j];
            if constexpr (EPI == 1)      C[off] = gelu_tanh(val + bias[nbase + j]);
            else if constexpr (EPI == 2) C[off] = fmaxf(val, 0.0f);
            else if constexpr (EPI == 3) C[off] = C[off] + val + bias[nbase + j];
            else if constexpr (EPI == 4) C[off] = C[off] + val;
            else                         C[off] = val;
        }
    }
}

// ---------------------------------------------------------------------------
// Launch
// ---------------------------------------------------------------------------
extern "C" void kernel_launch(void* const* d_in, const int* in_sizes, int n_in,
                              void* d_out, int out_size) {
    (void)in_sizes; (void)n_in; (void)out_size;
    const int*   ids     = (const int*)  d_in[0];
    const float* embed   = (const float*)d_in[1];
    const float* ln1_g   = (const float*)d_in[2];
    const float* ln1_b   = (const float*)d_in[3];
    const float* tm_ln_g = (const float*)d_in[4];
    const float* tm_ln_b = (const float*)d_in[5];
    const float* q_a     = (const float*)d_in[6];
    const float* q_b     = (const float*)d_in[7];
    const float* k_a     = (const float*)d_in[8];
    const float* k_b     = (const float*)d_in[9];
    const float* v_a     = (const float*)d_in[10];
    const float* v_b     = (const float*)d_in[11];
    const float* out_w   = (const float*)d_in[12];
    const float* out_b   = (const float*)d_in[13];
    const float* t_decay = (const float*)d_in[14];
    const float* ln2_g   = (const float*)d_in[15];
    const float* ln2_b   = (const float*)d_in[16];
    const float* ad_down = (const float*)d_in[17];
    const float* ad_up   = (const float*)d_in[18];
    const float* ffn_w1  = (const float*)d_in[19];
    const float* ffn_b1  = (const float*)d_in[20];
    const float* ffn_w2  = (const float*)d_in[21];
    const float* ffn_b2  = (const float*)d_in[22];
    const float* lnf_g   = (const float*)d_in[23];
    const float* lnf_b   = (const float*)d_in[24];
    float* out = (float*)d_out;

    float *x, *xm, *mixb, *qb, *kb, *vb, *yb, *x2, *ffn, *tq, *tk, *tv, *ad;
    cudaGetSymbolAddress((void**)&x,    g_x);
    cudaGetSymbolAddress((void**)&xm,   g_xm);
    cudaGetSymbolAddress((void**)&mixb, g_mix);
    cudaGetSymbolAddress((void**)&qb,   g_q);
    cudaGetSymbolAddress((void**)&kb,   g_k);
    cudaGetSymbolAddress((void**)&vb,   g_v);
    cudaGetSymbolAddress((void**)&yb,   g_y);
    cudaGetSymbolAddress((void**)&x2,   g_x2);
    cudaGetSymbolAddress((void**)&ffn,  g_ffn);
    cudaGetSymbolAddress((void**)&tq,   g_tq);
    cudaGetSymbolAddress((void**)&tk,   g_tk);
    cudaGetSymbolAddress((void**)&tv,   g_tv);
    cudaGetSymbolAddress((void**)&ad,   g_ad);

    gather_kernel<<<MM, 128>>>(ids, embed, x);

    const dim3 gBig(CC / 128, MM / 128);      // N=512 GEMMs
    const dim3 gFfn1(FFNN / 128, MM / 128);   // N=2048
    const dim3 g64(1, MM / 128);              // N=64
    const dim3 g32(1, MM / 128);              // N=32
    const dim3 gHead(VV / 64, MM / 128);      // N=8000 with BN=64

    for (int i = 0; i < LL; i++) {
        int g = i / 4;  // GROUP=4
        // --- time mixing ---
        ln12_kernel<<<MM, 256>>>(x, ln1_g + i * CC, ln1_b + i * CC,
                                 tm_ln_g + i * CC, tm_ln_b + i * CC, xm);
        mix_kernel<<<(MM * CC) / 256, 256>>>(xm, mixb);

        sgemm_kernel<128, 64, 16, 8, 4, 0, false><<<g64, 256>>>(mixb, q_a + (size_t)i * CC * RR, nullptr, tq, MM, RR, CC);
        sgemm_kernel<128, 64, 16, 8, 4, 0, false><<<g64, 256>>>(mixb, k_a + (size_t)i * CC * RR, nullptr, tk, MM, RR, CC);
        sgemm_kernel<128, 64, 16, 8, 4, 0, false><<<g64, 256>>>(mixb, v_a + (size_t)i * CC * RR, nullptr, tv, MM, RR, CC);

        sgemm_kernel<128, 128, 16, 8, 8, 0, false><<<gBig, 256>>>(tq, q_b + (size_t)i * RR * CC, nullptr, qb, MM, CC, RR);
        sgemm_kernel<128, 128, 16, 8, 8, 0, false><<<gBig, 256>>>(tk, k_b + (size_t)i * RR * CC, nullptr, kb, MM, CC, RR);
        sgemm_kernel<128, 128, 16, 8, 8, 0, false><<<gBig, 256>>>(tv, v_b + (size_t)i * RR * CC, nullptr, vb, MM, CC, RR);

        wkv_kernel<<<16, 256>>>(qb, kb, vb, t_decay + i * CC, yb,
                                out + LOGITS_ELEMS + (size_t)i * BB * CC);

        // x += y @ out_w + out_b
        sgemm_kernel<128, 128, 16, 8, 8, 3, false><<<gBig, 256>>>(yb, out_w + (size_t)i * CC * CC, out_b + i * CC, x, MM, CC, CC);

        // --- shared FFN ---
        ln_kernel<<<MM, 256>>>(x, ln2_g + i * CC, ln2_b + i * CC, x2);
        sgemm_kernel<128, 128, 16, 8, 8, 1, false><<<gFfn1, 256>>>(x2, ffn_w1 + (size_t)g * CC * FFNN, ffn_b1 + g * FFNN, ffn, MM, FFNN, CC);
        sgemm_kernel<128, 128, 16, 8, 8, 3, false><<<gBig, 256>>>(ffn, ffn_w2 + (size_t)g * FFNN * CC, ffn_b2 + g * CC, x, MM, CC, FFNN);

        // --- language adapter ---
        sgemm_kernel<128, 32, 16, 8, 2, 2, false><<<g32, 256>>>(x, ad_down + (size_t)i * CC * ARR, nullptr, ad, MM, ARR, CC);
        sgemm_kernel<128, 128, 16, 8, 8, 4, false><<<gBig, 256>>>(ad, ad_up + (size_t)i * ARR * CC, nullptr, x, MM, CC, ARR);
    }

    // --- final LN + tied head (C = x2 @ embed^T) ---
    ln_kernel<<<MM, 256>>>(x, lnf_g, lnf_b, x2);
    sgemm_kernel<128, 64, 16, 8, 4, 0, true><<<gHead, 256>>>(x2, embed, nullptr, out, MM, VV, CC);
}

// round 2
// speedup vs baseline: 2.1229x; 2.1229x over previous
#include <cuda_runtime.h>
#include <cstdint>
#include <cstddef>

// ---------------------------------------------------------------------------
// Problem dims
// ---------------------------------------------------------------------------
#define BB    8
#define TT    1024
#define CC    512
#define LL    12
#define VV    8000
#define RR    64
#define ARR   32
#define FFNN  2048
#define MM    (BB * TT)                  // 8192
#define LOGITS_ELEMS ((size_t)MM * VV)   // 65,536,000

// ---------------------------------------------------------------------------
// Scratch
// ---------------------------------------------------------------------------
__device__ float g_x  [MM * CC];
__device__ float g_xm [MM * CC];
__device__ float g_mix[MM * CC];
__device__ float g_q  [MM * CC];
__device__ float g_k  [MM * CC];
__device__ float g_v  [MM * CC];
__device__ float g_y  [MM * CC];
__device__ float g_x2 [MM * CC];
__device__ float g_ffn[MM * FFNN];
__device__ float g_tq [MM * RR];
__device__ float g_tk [MM * RR];
__device__ float g_tv [MM * RR];
__device__ float g_ad [MM * ARR];

// ---------------------------------------------------------------------------
// Small helpers
// ---------------------------------------------------------------------------
__device__ __forceinline__ float gelu_tanh(float x) {
    float x3 = x * x * x;
    return 0.5f * x * (1.0f + tanhf(0.7978845608028654f * (x + 0.044715f * x3)));
}

__device__ __forceinline__ uint32_t f2tf32(float f) {
    uint32_t u;
    asm("cvt.rna.tf32.f32 %0, %1;" : "=r"(u) : "f"(f));
    return u;
}

__device__ __forceinline__ void mma_tf32(float* c, const uint32_t* a, const uint32_t* b) {
    asm volatile(
        "mma.sync.aligned.m16n8k8.row.col.f32.tf32.tf32.f32 "
        "{%0,%1,%2,%3}, {%4,%5,%6,%7}, {%8,%9}, {%0,%1,%2,%3};\n"
        : "+f"(c[0]), "+f"(c[1]), "+f"(c[2]), "+f"(c[3])
        : "r"(a[0]), "r"(a[1]), "r"(a[2]), "r"(a[3]), "r"(b[0]), "r"(b[1]));
}

__device__ __forceinline__ float blockReduceSum(float v) {
    static __shared__ float sb[8];
    int tid = threadIdx.x;
#pragma unroll
    for (int o = 16; o > 0; o >>= 1) v += __shfl_down_sync(0xffffffffu, v, o);
    __syncthreads();
    if ((tid & 31) == 0) sb[tid >> 5] = v;
    __syncthreads();
    if (tid < 32) {
        v = (tid < 8) ? sb[tid] : 0.0f;
#pragma unroll
        for (int o = 4; o > 0; o >>= 1) v += __shfl_down_sync(0xffffffffu, v, o);
        if (tid == 0) sb[0] = v;
    }
    __syncthreads();
    return sb[0];
}

// ---------------------------------------------------------------------------
// Elementwise / LN / WKV kernels
// ---------------------------------------------------------------------------
__global__ void gather_kernel(const int* __restrict__ ids,
                              const float* __restrict__ embed,
                              float* __restrict__ x) {
    int r = blockIdx.x;
    int id = ids[r];
    const float4* er = (const float4*)(embed + (size_t)id * CC);
    float4* xr = (float4*)(x + (size_t)r * CC);
    xr[threadIdx.x] = er[threadIdx.x];
}

__global__ void ln12_kernel(const float* __restrict__ x,
                            const float* __restrict__ g1, const float* __restrict__ b1,
                            const float* __restrict__ g2, const float* __restrict__ b2,
                            float* __restrict__ out) {
    int r = blockIdx.x, tid = threadIdx.x;
    const float* xr = x + (size_t)r * CC;
    float a0 = xr[tid], a1 = xr[tid + 256];

    float m = blockReduceSum(a0 + a1) * (1.0f / CC);
    float d0 = a0 - m, d1 = a1 - m;
    float var = blockReduceSum(d0 * d0 + d1 * d1) * (1.0f / CC);
    float inv = rsqrtf(var + 1e-5f);
    float xi0 = d0 * inv * g1[tid]       + b1[tid];
    float xi1 = d1 * inv * g1[tid + 256] + b1[tid + 256];

    float m2 = blockReduceSum(xi0 + xi1) * (1.0f / CC);
    float e0 = xi0 - m2, e1 = xi1 - m2;
    float var2 = blockReduceSum(e0 * e0 + e1 * e1) * (1.0f / CC);
    float inv2 = rsqrtf(var2 + 1e-5f);
    out[(size_t)r * CC + tid]       = e0 * inv2 * g2[tid]       + b2[tid];
    out[(size_t)r * CC + tid + 256] = e1 * inv2 * g2[tid + 256] + b2[tid + 256];
}

__global__ void ln_kernel(const float* __restrict__ x,
                          const float* __restrict__ g, const float* __restrict__ b,
                          float* __restrict__ out) {
    int r = blockIdx.x, tid = threadIdx.x;
    const float* xr = x + (size_t)r * CC;
    float a0 = xr[tid], a1 = xr[tid + 256];
    float m = blockReduceSum(a0 + a1) * (1.0f / CC);
    float d0 = a0 - m, d1 = a1 - m;
    float var = blockReduceSum(d0 * d0 + d1 * d1) * (1.0f / CC);
    float inv = rsqrtf(var + 1e-5f);
    out[(size_t)r * CC + tid]       = d0 * inv * g[tid]       + b[tid];
    out[(size_t)r * CC + tid + 256] = d1 * inv * g[tid + 256] + b[tid + 256];
}

__global__ void mix_kernel(const float* __restrict__ xm, float* __restrict__ mix) {
    size_t idx = (size_t)blockIdx.x * blockDim.x + threadIdx.x;
    int m = (int)(idx >> 9);
    float v = 0.5f * xm[idx];
    if (m & (TT - 1)) v += 0.5f * xm[idx - CC];
    mix[idx] = v;
}

__global__ void wkv_kernel(const float* __restrict__ q,
                           const float* __restrict__ k,
                           const float* __restrict__ v,
                           const float* __restrict__ time_decay,
                           float* __restrict__ y,
                           float* __restrict__ hout) {
    int idx = blockIdx.x * blockDim.x + threadIdx.x;  // 0..4095
    int b = idx >> 9;
    int c = idx & (CC - 1);
    float d = expf(-expf(time_decay[c]));
    size_t base = (size_t)b * TT * CC + c;
    const float* qp = q + base;
    const float* kp = k + base;
    const float* vp = v + base;
    float* yp = y + base;
    float h = 0.0f;
#pragma unroll 4
    for (int t = 0; t < TT; t++) {
        size_t off = (size_t)t * CC;
        float qt = qp[off], kt = kp[off], vt = vp[off];
        h = d * h + kt * vt;
        yp[off] = h / (1.0f + expf(-qt));
    }
    hout[idx] = h;
}

// ---------------------------------------------------------------------------
// TF32 tensor-core GEMM.
//   C[M,N] (+)= A[M,K] * op(B)   (BT: B stored [N,K] -> C = A*B^T)
//   EPI: 0 store | 1 gelu(acc+bias) | 2 relu | 3 C += acc+bias | 4 C += acc
// 256 threads, warps 2(m) x 4(n). BM=128. BN in {128,64,32}. BK=32.
// All dims divide tiles exactly.
// ---------------------------------------------------------------------------
template<int BM, int BN, int BK, int EPI, bool BT>
__device__ __forceinline__ void gemm_body(
        const float* __restrict__ A, const float* __restrict__ B,
        const float* __restrict__ bias, float* __restrict__ C,
        int M, int N, int K, int m0, int n0) {
    constexpr int WM = BM / 2;       // 64
    constexpr int WN = BN / 4;       // 32/16/8
    constexpr int MF = WM / 16;      // 4
    constexpr int NF = WN / 8;       // 4/2/1
    constexpr int AV = BM * BK / (4 * 256);
    constexpr int BV = BK * BN / (4 * 256);
    constexpr int KV_A = BK / 4;     // 8
    constexpr int NV_B = BN / 4;

    __shared__ uint32_t As[BK][BM + 8];
    __shared__ uint32_t Bs[BK][BN + 8];

    const int tid  = threadIdx.x;
    const int lane = tid & 31;
    const int w    = tid >> 5;
    const int wm   = w & 1;
    const int wn   = w >> 1;
    const int lr   = lane >> 2;   // 0..7
    const int lc   = lane & 3;    // 0..3

    float acc[MF][NF][4];
#pragma unroll
    for (int i = 0; i < MF; i++)
#pragma unroll
        for (int j = 0; j < NF; j++)
#pragma unroll
            for (int t = 0; t < 4; t++) acc[i][j][t] = 0.0f;

    float4 pa[AV], pb[BV];

    auto ldg = [&](int k0) {
#pragma unroll
        for (int i = 0; i < AV; i++) {
            int id = tid + i * 256;
            int m = id / KV_A, kv = id % KV_A;
            pa[i] = *(const float4*)&A[(size_t)(m0 + m) * K + k0 + kv * 4];
        }
        if (!BT) {
#pragma unroll
            for (int i = 0; i < BV; i++) {
                int id = tid + i * 256;
                int k = id / NV_B, nv = id % NV_B;
                pb[i] = *(const float4*)&B[(size_t)(k0 + k) * N + n0 + nv * 4];
            }
        } else {
#pragma unroll
            for (int i = 0; i < BV; i++) {
                int id = tid + i * 256;
                int n = id / KV_A, kv = id % KV_A;
                pb[i] = *(const float4*)&B[(size_t)(n0 + n) * K + k0 + kv * 4];
            }
        }
    };

    auto sts = [&]() {
#pragma unroll
        for (int i = 0; i < AV; i++) {
            int id = tid + i * 256;
            int m = id / KV_A, kv = id % KV_A;
            As[kv * 4 + 0][m] = f2tf32(pa[i].x);
            As[kv * 4 + 1][m] = f2tf32(pa[i].y);
            As[kv * 4 + 2][m] = f2tf32(pa[i].z);
            As[kv * 4 + 3][m] = f2tf32(pa[i].w);
        }
        if (!BT) {
#pragma unroll
            for (int i = 0; i < BV; i++) {
                int id = tid + i * 256;
                int k = id / NV_B, nv = id % NV_B;
                uint4 t;
                t.x = f2tf32(pb[i].x); t.y = f2tf32(pb[i].y);
                t.z = f2tf32(pb[i].z); t.w = f2tf32(pb[i].w);
                *(uint4*)&Bs[k][nv * 4] = t;
            }
        } else {
#pragma unroll
            for (int i = 0; i < BV; i++) {
                int id = tid + i * 256;
                int n = id / KV_A, kv = id % KV_A;
                Bs[kv * 4 + 0][n] = f2tf32(pb[i].x);
                Bs[kv * 4 + 1][n] = f2tf32(pb[i].y);
                Bs[kv * 4 + 2][n] = f2tf32(pb[i].z);
                Bs[kv * 4 + 3][n] = f2tf32(pb[i].w);
            }
        }
    };

    auto compute = [&]() {
#pragma unroll
        for (int ks = 0; ks < BK / 8; ks++) {
            uint32_t af[MF][4], bf[NF][2];
            const int kk = ks * 8 + lc;
#pragma unroll
            for (int mt = 0; mt < MF; mt++) {
                const int mr = wm * WM + mt * 16 + lr;
                af[mt][0] = As[kk][mr];
                af[mt][1] = As[kk][mr + 8];
                af[mt][2] = As[kk + 4][mr];
                af[mt][3] = As[kk + 4][mr + 8];
            }
#pragma unroll
            for (int nt = 0; nt < NF; nt++) {
                const int nc = wn * WN + nt * 8 + lr;
                bf[nt][0] = Bs[kk][nc];
                bf[nt][1] = Bs[kk + 4][nc];
            }
#pragma unroll
            for (int mt = 0; mt < MF; mt++)
#pragma unroll
                for (int nt = 0; nt < NF; nt++)
                    mma_tf32(acc[mt][nt], af[mt], bf[nt]);
        }
    };

    ldg(0);
    sts();
    __syncthreads();
    for (int k0 = BK; k0 < K; k0 += BK) {
        ldg(k0);
        compute();
        __syncthreads();
        sts();
        __syncthreads();
    }
    compute();

    // epilogue
#pragma unroll
    for (int mt = 0; mt < MF; mt++) {
#pragma unroll
        for (int nt = 0; nt < NF; nt++) {
            const int gm0 = m0 + wm * WM + mt * 16 + lr;
            const int gn  = n0 + wn * WN + nt * 8 + lc * 2;
#pragma unroll
            for (int h = 0; h < 2; h++) {
                const int gm = gm0 + h * 8;
                size_t off = (size_t)gm * N + gn;
                float v0 = acc[mt][nt][h * 2];
                float v1 = acc[mt][nt][h * 2 + 1];
                if constexpr (EPI == 0) {
                    float2 o; o.x = v0; o.y = v1;
                    *(float2*)&C[off] = o;
                } else if constexpr (EPI == 1) {
                    float2 o;
                    o.x = gelu_tanh(v0 + bias[gn]);
                    o.y = gelu_tanh(v1 + bias[gn + 1]);
                    *(float2*)&C[off] = o;
                } else if constexpr (EPI == 2) {
                    float2 o; o.x = fmaxf(v0, 0.0f); o.y = fmaxf(v1, 0.0f);
                    *(float2*)&C[off] = o;
                } else if constexpr (EPI == 3) {
                    float2 c = *(float2*)&C[off];
                    c.x += v0 + bias[gn];
                    c.y += v1 + bias[gn + 1];
                    *(float2*)&C[off] = c;
                } else {
                    float2 c = *(float2*)&C[off];
                    c.x += v0; c.y += v1;
                    *(float2*)&C[off] = c;
                }
            }
        }
    }
}

template<int BM, int BN, int BK, int EPI, bool BT>
__global__ __launch_bounds__(256) void tf32_gemm(
        const float* __restrict__ A, const float* __restrict__ B,
        const float* __restrict__ bias, float* __restrict__ C,
        int M, int N, int K) {
    gemm_body<BM, BN, BK, EPI, BT>(A, B, bias, C, M, N, K,
                                   blockIdx.y * BM, blockIdx.x * BN);
}

// Three independent GEMMs selected by blockIdx.z: Cz = Az * Bz (shared shapes)
template<int BM, int BN, int BK>
__global__ __launch_bounds__(256) void tf32_gemm3(
        const float* __restrict__ A0, const float* __restrict__ A1, const float* __restrict__ A2,
        const float* __restrict__ B0, const float* __restrict__ B1, const float* __restrict__ B2,
        float* __restrict__ C0, float* __restrict__ C1, float* __restrict__ C2,
        int M, int N, int K) {
    const float* A = (blockIdx.z == 0) ? A0 : (blockIdx.z == 1) ? A1 : A2;
    const float* B = (blockIdx.z == 0) ? B0 : (blockIdx.z == 1) ? B1 : B2;
    float*       C = (blockIdx.z == 0) ? C0 : (blockIdx.z == 1) ? C1 : C2;
    gemm_body<BM, BN, BK, 0, false>(A, B, nullptr, C, M, N, K,
                                    blockIdx.y * BM, blockIdx.x * BN);
}

// ---------------------------------------------------------------------------
// Launch
// ---------------------------------------------------------------------------
extern "C" void kernel_launch(void* const* d_in, const int* in_sizes, int n_in,
                              void* d_out, int out_size) {
    (void)in_sizes; (void)n_in; (void)out_size;
    const int*   ids     = (const int*)  d_in[0];
    const float* embed   = (const float*)d_in[1];
    const float* ln1_g   = (const float*)d_in[2];
    const float* ln1_b   = (const float*)d_in[3];
    const float* tm_ln_g = (const float*)d_in[4];
    const float* tm_ln_b = (const float*)d_in[5];
    const float* q_a     = (const float*)d_in[6];
    const float* q_b     = (const float*)d_in[7];
    const float* k_a     = (const float*)d_in[8];
    const float* k_b     = (const float*)d_in[9];
    const float* v_a     = (const float*)d_in[10];
    const float* v_b     = (const float*)d_in[11];
    const float* out_w   = (const float*)d_in[12];
    const float* out_b   = (const float*)d_in[13];
    const float* t_decay = (const float*)d_in[14];
    const float* ln2_g   = (const float*)d_in[15];
    const float* ln2_b   = (const float*)d_in[16];
    const float* ad_down = (const float*)d_in[17];
    const float* ad_up   = (const float*)d_in[18];
    const float* ffn_w1  = (const float*)d_in[19];
    const float* ffn_b1  = (const float*)d_in[20];
    const float* ffn_w2  = (const float*)d_in[21];
    const float* ffn_b2  = (const float*)d_in[22];
    const float* lnf_g   = (const float*)d_in[23];
    const float* lnf_b   = (const float*)d_in[24];
    float* out = (float*)d_out;

    float *x, *xm, *mixb, *qb, *kb, *vb, *yb, *x2, *ffn, *tq, *tk, *tv, *ad;
    cudaGetSymbolAddress((void**)&x,    g_x);
    cudaGetSymbolAddress((void**)&xm,   g_xm);
    cudaGetSymbolAddress((void**)&mixb, g_mix);
    cudaGetSymbolAddress((void**)&qb,   g_q);
    cudaGetSymbolAddress((void**)&kb,   g_k);
    cudaGetSymbolAddress((void**)&vb,   g_v);
    cudaGetSymbolAddress((void**)&yb,   g_y);
    cudaGetSymbolAddress((void**)&x2,   g_x2);
    cudaGetSymbolAddress((void**)&ffn,  g_ffn);
    cudaGetSymbolAddress((void**)&tq,   g_tq);
    cudaGetSymbolAddress((void**)&tk,   g_tk);
    cudaGetSymbolAddress((void**)&tv,   g_tv);
    cudaGetSymbolAddress((void**)&ad,   g_ad);

    gather_kernel<<<MM, 128>>>(ids, embed, x);

    const dim3 gBig(CC / 128, MM / 128);          // N=512, BN=128
    const dim3 gFfn1(FFNN / 128, MM / 128);       // N=2048
    const dim3 gQKVa(1, MM / 128, 3);             // N=64, BN=64
    const dim3 gQKVb(CC / 128, MM / 128, 3);      // N=512, BN=128
    const dim3 gAd(1, MM / 128);                  // N=32, BN=32
    const dim3 gHead(VV / 64, MM / 128);          // N=8000, BN=64

    for (int i = 0; i < LL; i++) {
        int g = i / 4;  // GROUP=4
        // --- time mixing ---
        ln12_kernel<<<MM, 256>>>(x, ln1_g + i * CC, ln1_b + i * CC,
                                 tm_ln_g + i * CC, tm_ln_b + i * CC, xm);
        mix_kernel<<<(MM * CC) / 256, 256>>>(xm, mixb);

        // q/k/v low-rank down-projections (shared A = mix)
        tf32_gemm3<128, 64, 32><<<gQKVa, 256>>>(
            mixb, mixb, mixb,
            q_a + (size_t)i * CC * RR, k_a + (size_t)i * CC * RR, v_a + (size_t)i * CC * RR,
            tq, tk, tv, MM, RR, CC);
        // q/k/v low-rank up-projections (distinct A per z)
        tf32_gemm3<128, 128, 32><<<gQKVb, 256>>>(
            tq, tk, tv,
            q_b + (size_t)i * RR * CC, k_b + (size_t)i * RR * CC, v_b + (size_t)i * RR * CC,
            qb, kb, vb, MM, CC, RR);

        wkv_kernel<<<16, 256>>>(qb, kb, vb, t_decay + i * CC, yb,
                                out + LOGITS_ELEMS + (size_t)i * BB * CC);

        tf32_gemm<128, 128, 32, 3, false><<<gBig, 256>>>(
            yb, out_w + (size_t)i * CC * CC, out_b + i * CC, x, MM, CC, CC);

        // --- shared FFN ---
        ln_kernel<<<MM, 256>>>(x, ln2_g + i * CC, ln2_b + i * CC, x2);
        tf32_gemm<128, 128, 32, 1, false><<<gFfn1, 256>>>(
            x2, ffn_w1 + (size_t)g * CC * FFNN, ffn_b1 + g * FFNN, ffn, MM, FFNN, CC);
        tf32_gemm<128, 128, 32, 3, false><<<gBig, 256>>>(
            ffn, ffn_w2 + (size_t)g * FFNN * CC, ffn_b2 + g * CC, x, MM, CC, FFNN);

        // --- language adapter ---
        tf32_gemm<128, 32, 32, 2, false><<<gAd, 256>>>(
            x, ad_down + (size_t)i * CC * ARR, nullptr, ad, MM, ARR, CC);
        tf32_gemm<128, 128, 32, 4, false><<<gBig, 256>>>(
            ad, ad_up + (size_t)i * ARR * CC, nullptr, x, MM, CC, ARR);
    }

    // --- final LN + tied head ---
    ln_kernel<<<MM, 256>>>(x, lnf_g, lnf_b, x2);
    tf32_gemm<128, 64, 32, 0, true><<<gHead, 256>>>(x2, embed, nullptr, out, MM, VV, CC);
}